// round 12
// baseline (speedup 1.0000x reference)
#include <cuda_runtime.h>

// ---------------------------------------------------------------------------
// Persistent fused LSTM, feedback algebraically absorbed:
//   W_eff = W_hh + W_ih (outer) W_lin,  b_eff = b_ih + b_hh + W_ih * b_lin
// 128 CTAs x 256 threads; CTA owns batches (2c, 2c+1).
// Unit-owner mapping: thread (p=t>>1, ks=t&1) computes gates {i,f,g,o} of
// unit p, k-half ks, both batches; xor1 completes sums; same thread updates
// (batch=ks, j=p). ONE barrier/step; y-reduction deferred past the barrier.
// R11: warp-level y sums (4 shfls -> 1 partial/warp/batch); out-store is
// 1 LDS + 3 shfls on warp 0 -> minimal pre-matvec skew at the barrier.
// ---------------------------------------------------------------------------

typedef unsigned long long ull;

#define THREADS 256
#define T_STEPS 2048
#define NB      256

// SMEM layout (float offsets)
#define KH       68                    // k-half stride (64 + 4 pad)
#define W_PITCH  136                   // weight row pitch -> LDS phases hit granules 0..7
#define WS_OFF   0                     // 256 rows (g,o gates) x 136 = 34816
#define HBUF     34816                 // [2 parity][2 batch x 144]
#define HB_B     144
#define HB_PAR   288
#define YBUF     (HBUF + 2*HB_PAR)     // [2 slot][2 batch][8 warp partials]
#define SMEM_FLOATS (YBUF + 32)
#define SMEM_BYTES  (SMEM_FLOATS * 4)

__device__ __forceinline__ ull pk2(float x, float y) {
    ull r; asm("mov.b64 %0, {%1, %2};" : "=l"(r) : "f"(x), "f"(y)); return r;
}
__device__ __forceinline__ float2 upk2(ull v) {
    float2 f; asm("mov.b64 {%0, %1}, %2;" : "=f"(f.x), "=f"(f.y) : "l"(v)); return f;
}
__device__ __forceinline__ ull ffma2(ull a, ull b, ull c) {
    ull d; asm("fma.rn.f32x2 %0, %1, %2, %3;" : "=l"(d) : "l"(a), "l"(b), "l"(c)); return d;
}
__device__ __forceinline__ float tanha(float x) {
    float y; asm("tanh.approx.f32 %0, %1;" : "=f"(y) : "f"(x)); return y;
}
__device__ __forceinline__ float siga(float x) {
    return fmaf(0.5f, tanha(0.5f * x), 0.5f);
}

// One LSTM step. PARV = parity (reads h[PARV], writes h[PARV^1]).
// DOY: reduce previous step's y into YBUF slot (PARV^1).
// DOOUT: store out[step-2] from YBUF slot (PARV). EXTRA: step-0 correction.
#define STEP_BODY(PARV, DOY, DOOUT, ...)                                          \
    {                                                                             \
        if (DOY) {   /* warp-level y sum for previous h; overlaps matvec LDS */   \
            float py = hn_prev * wlin_p;                                          \
            py += __shfl_xor_sync(0xffffffffu, py, 2);                            \
            py += __shfl_xor_sync(0xffffffffu, py, 4);                            \
            py += __shfl_xor_sync(0xffffffffu, py, 8);                            \
            py += __shfl_xor_sync(0xffffffffu, py, 16);                           \
            if (lane < 2)                                                         \
                sm[YBUF + ((PARV) ^ 1) * 16 + lane * 8 + (t >> 5)] = py;          \
        }                                                                         \
        if (DOOUT && t < 32) {   /* out[step-2]: 1 LDS + 3 shfls on warp 0 */     \
            int bb = lane >> 4;                                                   \
            float v = ((lane & 15) < 8)                                           \
                    ? sm[YBUF + (PARV) * 16 + bb * 8 + (lane & 7)] : 0.0f;        \
            v += __shfl_xor_sync(0xffffffffu, v, 1);                              \
            v += __shfl_xor_sync(0xffffffffu, v, 2);                              \
            v += __shfl_xor_sync(0xffffffffu, v, 4);                              \
            if ((lane & 15) == 0)                                                 \
                out[(step - 2) * NB + 2 * cta + bb] = v + blin;                   \
        }                                                                         \
        const float* hbase = sm + HBUF + ((PARV) ? HB_PAR : 0);                   \
        const ulonglong2* H0 = (const ulonglong2*)(hbase + ks * KH);              \
        const ulonglong2* H1 = (const ulonglong2*)(hbase + HB_B + ks * KH);       \
        ull ai0 = 0, ai1 = 0, af0 = 0, af1 = 0, ag0 = 0, ag1 = 0, ao0 = 0, ao1 = 0; \
        _Pragma("unroll")                                                         \
        for (int c = 0; c < 2; ++c) {                                             \
            ulonglong2 hv0 = H0[c];                                               \
            ulonglong2 hv1 = H1[c];                                               \
            ull wia = wri[2 * c], wib = wri[2 * c + 1];                           \
            ull wfa = wrf[2 * c], wfb = wrf[2 * c + 1];                           \
            ull wga = wgx[2 * c], wgb = wgx[2 * c + 1];                           \
            ull woa = wox[2 * c], wob = wox[2 * c + 1];                           \
            ai0 = ffma2(wia, hv0.x, ai0); ai0 = ffma2(wib, hv0.y, ai0);           \
            ai1 = ffma2(wia, hv1.x, ai1); ai1 = ffma2(wib, hv1.y, ai1);           \
            af0 = ffma2(wfa, hv0.x, af0); af0 = ffma2(wfb, hv0.y, af0);           \
            af1 = ffma2(wfa, hv1.x, af1); af1 = ffma2(wfb, hv1.y, af1);           \
            ag0 = ffma2(wga, hv0.x, ag0); ag0 = ffma2(wgb, hv0.y, ag0);           \
            ag1 = ffma2(wga, hv1.x, ag1); ag1 = ffma2(wgb, hv1.y, ag1);           \
            ao0 = ffma2(woa, hv0.x, ao0); ao0 = ffma2(wob, hv0.y, ao0);           \
            ao1 = ffma2(woa, hv1.x, ao1); ao1 = ffma2(wob, hv1.y, ao1);           \
        }                                                                         \
        _Pragma("unroll")                                                         \
        for (int c = 2; c < 16; ++c) {                                            \
            ulonglong2 hv0 = H0[c];                                               \
            ulonglong2 hv1 = H1[c];                                               \
            ulonglong2 w2  = W2[c];                                               \
            ulonglong2 w3  = W3[c];                                               \
            ull wia = wri[2 * c], wib = wri[2 * c + 1];                           \
            ull wfa = wrf[2 * c], wfb = wrf[2 * c + 1];                           \
            ai0 = ffma2(wia, hv0.x, ai0); ai0 = ffma2(wib, hv0.y, ai0);           \
            ai1 = ffma2(wia, hv1.x, ai1); ai1 = ffma2(wib, hv1.y, ai1);           \
            af0 = ffma2(wfa, hv0.x, af0); af0 = ffma2(wfb, hv0.y, af0);           \
            af1 = ffma2(wfa, hv1.x, af1); af1 = ffma2(wfb, hv1.y, af1);           \
            ag0 = ffma2(w2.x, hv0.x, ag0); ag0 = ffma2(w2.y, hv0.y, ag0);         \
            ag1 = ffma2(w2.x, hv1.x, ag1); ag1 = ffma2(w2.y, hv1.y, ag1);         \
            ao0 = ffma2(w3.x, hv0.x, ao0); ao0 = ffma2(w3.y, hv0.y, ao0);         \
            ao1 = ffma2(w3.x, hv1.x, ao1); ao1 = ffma2(w3.y, hv1.y, ao1);         \
        }                                                                         \
        float gI, gF, gG, gO;                                                     \
        {                                                                         \
            float2 f;                                                             \
            f = upk2(ai0); float si0 = f.x + f.y;                                 \
            f = upk2(ai1); float si1 = f.x + f.y;                                 \
            f = upk2(af0); float sf0 = f.x + f.y;                                 \
            f = upk2(af1); float sf1 = f.x + f.y;                                 \
            f = upk2(ag0); float sg0 = f.x + f.y;                                 \
            f = upk2(ag1); float sg1 = f.x + f.y;                                 \
            f = upk2(ao0); float so0 = f.x + f.y;                                 \
            f = upk2(ao1); float so1 = f.x + f.y;                                 \
            gI = (ks ? si1 : si0) + __shfl_xor_sync(0xffffffffu, ks ? si0 : si1, 1); \
            gF = (ks ? sf1 : sf0) + __shfl_xor_sync(0xffffffffu, ks ? sf0 : sf1, 1); \
            gG = (ks ? sg1 : sg0) + __shfl_xor_sync(0xffffffffu, ks ? sg0 : sg1, 1); \
            gO = (ks ? so1 : so0) + __shfl_xor_sync(0xffffffffu, ks ? so0 : so1, 1); \
        }                                                                         \
        gI += biasv[0];                                                           \
        gF += biasv[1];                                                           \
        gG += biasv[2];                                                           \
        gO += biasv[3];                                                           \
        __VA_ARGS__                                                               \
        {                                                                         \
            float iv = siga(gI);                                                  \
            float fv = siga(gF);                                                  \
            float gv = tanha(gG);                                                 \
            float ov = siga(gO);                                                  \
            c_state = fv * c_state + iv * gv;                                     \
            float hn = ov * tanha(c_state);                                       \
            sm[hwr0 + ((PARV) ? 0 : HB_PAR)] = hn;                                \
            hn_prev = hn;                                                         \
        }                                                                         \
        __syncthreads();                                                          \
    }

__global__ void __launch_bounds__(THREADS, 1)
lstm_seq_kernel(float* __restrict__ out,
                const int*   __restrict__ label,
                const float* __restrict__ h0,
                const float* __restrict__ W_ih,
                const float* __restrict__ W_hh,
                const float* __restrict__ b_ih,
                const float* __restrict__ b_hh,
                const float* __restrict__ W_lin,
                const float* __restrict__ b_lin)
{
    extern __shared__ float sm[];
    const int t    = threadIdx.x;
    const int cta  = blockIdx.x;
    const int p    = t >> 1;      // hidden unit 0..127
    const int ks   = t & 1;       // k half == batch this thread updates
    const int lane = t & 31;
    const float blin = b_lin[0];

    // ---- one-time init -----------------------------------------------------
    for (int idx = t; idx < 256 * 128; idx += THREADS) {
        int r = idx >> 7, k = idx & 127;
        sm[WS_OFF + r * W_PITCH + (k >> 6) * KH + (k & 63)] =
            W_hh[(256 + r) * 128 + k] + W_ih[256 + r] * W_lin[k];
    }
    {   // initial h -> parity 0
        int b = t >> 7, j = t & 127;
        int lab = label[2 * cta + b];
        sm[HBUF + b * HB_B + (j >> 6) * KH + (j & 63)] = h0[lab * 128 + j];
    }

    // Register weights: effective rows p (i), 128+p (f) full k-half, plus the
    // first 16 floats of the k-half of rows 256+p (g) and 384+p (o).
    ull wri[32], wrf[32], wgx[8], wox[8];
    {
        const float2* s0 = (const float2*)(W_hh + p * 128 + ks * 64);
        const float2* s1 = (const float2*)(W_hh + (128 + p) * 128 + ks * 64);
        const float2* s2 = (const float2*)(W_hh + (256 + p) * 128 + ks * 64);
        const float2* s3 = (const float2*)(W_hh + (384 + p) * 128 + ks * 64);
        const float2* wl = (const float2*)(W_lin + ks * 64);
        const float wih_i = W_ih[p], wih_f = W_ih[128 + p];
        const float wih_g = W_ih[256 + p], wih_o = W_ih[384 + p];
#pragma unroll
        for (int c = 0; c < 32; ++c) {
            float2 a = s0[c], b = s1[c], w = wl[c];
            wri[c] = pk2(fmaf(wih_i, w.x, a.x), fmaf(wih_i, w.y, a.y));
            wrf[c] = pk2(fmaf(wih_f, w.x, b.x), fmaf(wih_f, w.y, b.y));
        }
#pragma unroll
        for (int c = 0; c < 8; ++c) {
            float2 g = s2[c], o = s3[c], w = wl[c];
            wgx[c] = pk2(fmaf(wih_g, w.x, g.x), fmaf(wih_g, w.y, g.y));
            wox[c] = pk2(fmaf(wih_o, w.x, o.x), fmaf(wih_o, w.y, o.y));
        }
    }

    // per-unit constants
    float biasv[4];
    {
        int rows[4] = {p, 128 + p, 256 + p, 384 + p};
#pragma unroll
        for (int q = 0; q < 4; ++q)
            biasv[q] = b_ih[rows[q]] + b_hh[rows[q]] + W_ih[rows[q]] * blin;
    }
    const float wlin_p = W_lin[p];
    float c_state = 0.0f;
    float hn_prev = 0.0f;

    // constant pointers
    const ulonglong2* W2 = (const ulonglong2*)(sm + WS_OFF + p * W_PITCH + ks * KH);
    const ulonglong2* W3 = (const ulonglong2*)(sm + WS_OFF + (128 + p) * W_PITCH + ks * KH);
    const int hwr0 = HBUF + ks * HB_B + (p >> 6) * KH + (p & 63);

    __syncthreads();

    int step = 0;

    // ---- peeled step 0 (with one-time rank-1 correction) ---------------------
    {
        float xb;
        {
            float acc = 0.0f;
            const float* hb = sm + HBUF + ks * HB_B;
#pragma unroll 8
            for (int j = 0; j < 128; ++j)
                acc = fmaf(hb[(j >> 6) * KH + (j & 63)], W_lin[j], acc);
            xb = -(acc + blin);
        }
        const float w0 = W_ih[p], w1 = W_ih[128 + p],
                    w2c = W_ih[256 + p], w3c = W_ih[384 + p];
        STEP_BODY(0, false, false,
                  gI += xb * w0; gF += xb * w1; gG += xb * w2c; gO += xb * w3c;)
        ++step;
    }
    // ---- peeled step 1 -------------------------------------------------------
    STEP_BODY(1, true, false, ;)
    ++step;

    // ---- steps 2..2047: clean 2x-unrolled loop -------------------------------
#pragma unroll 1
    for (int it = 0; it < (T_STEPS - 2) / 2; ++it) {
        STEP_BODY(0, true, true, ;)
        ++step;
        STEP_BODY(1, true, true, ;)
        ++step;
    }

    // ---- epilogue: y for step T-1, then drain last two outputs --------------
    {
        float py = hn_prev * wlin_p;
        py += __shfl_xor_sync(0xffffffffu, py, 2);
        py += __shfl_xor_sync(0xffffffffu, py, 4);
        py += __shfl_xor_sync(0xffffffffu, py, 8);
        py += __shfl_xor_sync(0xffffffffu, py, 16);
        if (lane < 2)
            sm[YBUF + ((T_STEPS - 1) & 1) * 16 + lane * 8 + (t >> 5)] = py;
    }
    __syncthreads();
    if (t < 32) {
#pragma unroll
        for (int s = 0; s < 2; ++s) {       // steps T-2 (slot 0), T-1 (slot 1)
            int slot = (T_STEPS - 2 + s) & 1;
            int bb = lane >> 4;
            float v = ((lane & 15) < 8)
                    ? sm[YBUF + slot * 16 + bb * 8 + (lane & 7)] : 0.0f;
            v += __shfl_xor_sync(0xffffffffu, v, 1);
            v += __shfl_xor_sync(0xffffffffu, v, 2);
            v += __shfl_xor_sync(0xffffffffu, v, 4);
            if ((lane & 15) == 0)
                out[(T_STEPS - 2 + s) * NB + 2 * cta + bb] = v + blin;
        }
    }
}

extern "C" void kernel_launch(void* const* d_in, const int* in_sizes, int n_in,
                              void* d_out, int out_size) {
    // metadata order: input, label, h0, W_ih, W_hh, b_ih, b_hh, W_lin, b_lin
    const int*   label  = (const int*)  d_in[1];
    const float* h0     = (const float*)d_in[2];
    const float* W_ih   = (const float*)d_in[3];
    const float* W_hh   = (const float*)d_in[4];
    const float* b_ih   = (const float*)d_in[5];
    const float* b_hh   = (const float*)d_in[6];
    const float* W_lin  = (const float*)d_in[7];
    const float* b_lin  = (const float*)d_in[8];
    float* out = (float*)d_out;

    cudaFuncSetAttribute(lstm_seq_kernel,
                         cudaFuncAttributeMaxDynamicSharedMemorySize, SMEM_BYTES);
    lstm_seq_kernel<<<128, THREADS, SMEM_BYTES>>>(out, label, h0, W_ih, W_hh,
                                                  b_ih, b_hh, W_lin, b_lin);
}

// round 13
// speedup vs baseline: 1.0063x; 1.0063x over previous
#include <cuda_runtime.h>

// ---------------------------------------------------------------------------
// Persistent fused LSTM, feedback algebraically absorbed:
//   W_eff = W_hh + W_ih (outer) W_lin,  b_eff = b_ih + b_hh + W_ih * b_lin
// 128 CTAs x 256 threads; CTA owns batches (2c, 2c+1).
// Unit-owner: thread (p=t>>1, ks=t&1) computes gates {i,f,g,o} of unit p,
// k-half ks, both batches; xor1 completes sums; same thread updates
// (batch=ks, j=p). ONE barrier/step.
// R12: (a) SMSP-mate warps run the two matvec halves in opposite order to
// break scoreboard phase-locking; (b) y warp-partials go straight to a GMEM
// ring, folded by a tiny second kernel -- no YBUF/out work in the hot loop.
// ---------------------------------------------------------------------------

typedef unsigned long long ull;

#define THREADS 256
#define T_STEPS 2048
#define NB      256

// SMEM layout (float offsets)
#define KH       68                    // k-half stride (64 + 4 pad)
#define W_PITCH  136                   // weight row pitch -> LDS phases hit granules 0..7
#define WS_OFF   0                     // 256 rows (g,o gates) x 136 = 34816
#define HBUF     34816                 // [2 parity][2 batch x 144]
#define HB_B     144
#define HB_PAR   288
#define SMEM_FLOATS (HBUF + 2*HB_PAR)
#define SMEM_BYTES  (SMEM_FLOATS * 4)

// GMEM ring of per-warp y partials: [step][cta][batch*8 + warp]
__device__ float g_ypart[T_STEPS * 128 * 16];

__device__ __forceinline__ ull pk2(float x, float y) {
    ull r; asm("mov.b64 %0, {%1, %2};" : "=l"(r) : "f"(x), "f"(y)); return r;
}
__device__ __forceinline__ float2 upk2(ull v) {
    float2 f; asm("mov.b64 {%0, %1}, %2;" : "=f"(f.x), "=f"(f.y) : "l"(v)); return f;
}
__device__ __forceinline__ ull ffma2(ull a, ull b, ull c) {
    ull d; asm("fma.rn.f32x2 %0, %1, %2, %3;" : "=l"(d) : "l"(a), "l"(b), "l"(c)); return d;
}
__device__ __forceinline__ float tanha(float x) {
    float y; asm("tanh.approx.f32 %0, %1;" : "=f"(y) : "f"(x)); return y;
}
__device__ __forceinline__ float siga(float x) {
    return fmaf(0.5f, tanha(0.5f * x), 0.5f);
}

// One matvec half over iterations [LO, HI). c is compile-time inside the
// unrolled loop, so the c<2 register-weight path resolves statically.
#define MV_HALF(LO, HI)                                                           \
    _Pragma("unroll")                                                             \
    for (int c = (LO); c < (HI); ++c) {                                           \
        ulonglong2 hv0 = H0[c];                                                   \
        ulonglong2 hv1 = H1[c];                                                   \
        ull wga, wgb, woa, wob;                                                   \
        if (c < 2) {                                                              \
            wga = wgx[2 * c]; wgb = wgx[2 * c + 1];                               \
            woa = wox[2 * c]; wob = wox[2 * c + 1];                               \
        } else {                                                                  \
            ulonglong2 w2 = W2[c];                                                \
            ulonglong2 w3 = W3[c];                                                \
            wga = w2.x; wgb = w2.y; woa = w3.x; wob = w3.y;                       \
        }                                                                         \
        ull wia = wri[2 * c], wib = wri[2 * c + 1];                               \
        ull wfa = wrf[2 * c], wfb = wrf[2 * c + 1];                               \
        ai0 = ffma2(wia, hv0.x, ai0); ai0 = ffma2(wib, hv0.y, ai0);               \
        ai1 = ffma2(wia, hv1.x, ai1); ai1 = ffma2(wib, hv1.y, ai1);               \
        af0 = ffma2(wfa, hv0.x, af0); af0 = ffma2(wfb, hv0.y, af0);               \
        af1 = ffma2(wfa, hv1.x, af1); af1 = ffma2(wfb, hv1.y, af1);               \
        ag0 = ffma2(wga, hv0.x, ag0); ag0 = ffma2(wgb, hv0.y, ag0);               \
        ag1 = ffma2(wga, hv1.x, ag1); ag1 = ffma2(wgb, hv1.y, ag1);               \
        ao0 = ffma2(woa, hv0.x, ao0); ao0 = ffma2(wob, hv0.y, ao0);               \
        ao1 = ffma2(woa, hv1.x, ao1); ao1 = ffma2(wob, hv1.y, ao1);               \
    }

// One LSTM step. PARV = parity (reads h[PARV], writes h[PARV^1]).
// DOY: reduce previous step's y partials to GMEM. EXTRA: step-0 correction.
#define STEP_BODY(PARV, DOY, ...)                                                 \
    {                                                                             \
        if (DOY) {   /* warp y-sum for previous h; overlaps the matvec LDS */     \
            float py = hn_prev * wlin_p;                                          \
            py += __shfl_xor_sync(0xffffffffu, py, 2);                            \
            py += __shfl_xor_sync(0xffffffffu, py, 4);                            \
            py += __shfl_xor_sync(0xffffffffu, py, 8);                            \
            py += __shfl_xor_sync(0xffffffffu, py, 16);                           \
            if (lane < 2)   /* lane0=b0, lane1=b1 */                              \
                g_ypart[(step - 1) * 2048 + cta * 16 + lane * 8 + (t >> 5)] = py; \
        }                                                                         \
        const float* hbase = sm + HBUF + ((PARV) ? HB_PAR : 0);                   \
        const ulonglong2* H0 = (const ulonglong2*)(hbase + ks * KH);              \
        const ulonglong2* H1 = (const ulonglong2*)(hbase + HB_B + ks * KH);       \
        ull ai0 = 0, ai1 = 0, af0 = 0, af1 = 0, ag0 = 0, ag1 = 0, ao0 = 0, ao1 = 0; \
        if (wskew) { MV_HALF(8, 16) MV_HALF(0, 8) }                               \
        else       { MV_HALF(0, 8)  MV_HALF(8, 16) }                              \
        float gI, gF, gG, gO;                                                     \
        {                                                                         \
            float2 f;                                                             \
            f = upk2(ai0); float si0 = f.x + f.y;                                 \
            f = upk2(ai1); float si1 = f.x + f.y;                                 \
            f = upk2(af0); float sf0 = f.x + f.y;                                 \
            f = upk2(af1); float sf1 = f.x + f.y;                                 \
            f = upk2(ag0); float sg0 = f.x + f.y;                                 \
            f = upk2(ag1); float sg1 = f.x + f.y;                                 \
            f = upk2(ao0); float so0 = f.x + f.y;                                 \
            f = upk2(ao1); float so1 = f.x + f.y;                                 \
            gI = (ks ? si1 : si0) + __shfl_xor_sync(0xffffffffu, ks ? si0 : si1, 1); \
            gF = (ks ? sf1 : sf0) + __shfl_xor_sync(0xffffffffu, ks ? sf0 : sf1, 1); \
            gG = (ks ? sg1 : sg0) + __shfl_xor_sync(0xffffffffu, ks ? sg0 : sg1, 1); \
            gO = (ks ? so1 : so0) + __shfl_xor_sync(0xffffffffu, ks ? so0 : so1, 1); \
        }                                                                         \
        gI += biasv[0];                                                           \
        gF += biasv[1];                                                           \
        gG += biasv[2];                                                           \
        gO += biasv[3];                                                           \
        __VA_ARGS__                                                               \
        {                                                                         \
            float iv = siga(gI);                                                  \
            float fv = siga(gF);                                                  \
            float gv = tanha(gG);                                                 \
            float ov = siga(gO);                                                  \
            c_state = fv * c_state + iv * gv;                                     \
            float hn = ov * tanha(c_state);                                       \
            sm[hwr0 + ((PARV) ? 0 : HB_PAR)] = hn;                                \
            hn_prev = hn;                                                         \
        }                                                                         \
        __syncthreads();                                                          \
    }

__global__ void __launch_bounds__(THREADS, 1)
lstm_seq_kernel(const int*   __restrict__ label,
                const float* __restrict__ h0,
                const float* __restrict__ W_ih,
                const float* __restrict__ W_hh,
                const float* __restrict__ b_ih,
                const float* __restrict__ b_hh,
                const float* __restrict__ W_lin,
                const float* __restrict__ b_lin)
{
    extern __shared__ float sm[];
    const int t    = threadIdx.x;
    const int cta  = blockIdx.x;
    const int p    = t >> 1;      // hidden unit 0..127
    const int ks   = t & 1;       // k half == batch this thread updates
    const int lane = t & 31;
    const int wskew = (t >> 7) & 1;   // warps 0-3 vs 4-7: SMSP mates differ
    const float blin = b_lin[0];

    // ---- one-time init -----------------------------------------------------
    for (int idx = t; idx < 256 * 128; idx += THREADS) {
        int r = idx >> 7, k = idx & 127;
        sm[WS_OFF + r * W_PITCH + (k >> 6) * KH + (k & 63)] =
            W_hh[(256 + r) * 128 + k] + W_ih[256 + r] * W_lin[k];
    }
    {   // initial h -> parity 0
        int b = t >> 7, j = t & 127;
        int lab = label[2 * cta + b];
        sm[HBUF + b * HB_B + (j >> 6) * KH + (j & 63)] = h0[lab * 128 + j];
    }

    // Register weights: effective rows p (i), 128+p (f) full k-half, plus the
    // first 16 floats of the k-half of rows 256+p (g) and 384+p (o).
    ull wri[32], wrf[32], wgx[8], wox[8];
    {
        const float2* s0 = (const float2*)(W_hh + p * 128 + ks * 64);
        const float2* s1 = (const float2*)(W_hh + (128 + p) * 128 + ks * 64);
        const float2* s2 = (const float2*)(W_hh + (256 + p) * 128 + ks * 64);
        const float2* s3 = (const float2*)(W_hh + (384 + p) * 128 + ks * 64);
        const float2* wl = (const float2*)(W_lin + ks * 64);
        const float wih_i = W_ih[p], wih_f = W_ih[128 + p];
        const float wih_g = W_ih[256 + p], wih_o = W_ih[384 + p];
#pragma unroll
        for (int c = 0; c < 32; ++c) {
            float2 a = s0[c], b = s1[c], w = wl[c];
            wri[c] = pk2(fmaf(wih_i, w.x, a.x), fmaf(wih_i, w.y, a.y));
            wrf[c] = pk2(fmaf(wih_f, w.x, b.x), fmaf(wih_f, w.y, b.y));
        }
#pragma unroll
        for (int c = 0; c < 8; ++c) {
            float2 g = s2[c], o = s3[c], w = wl[c];
            wgx[c] = pk2(fmaf(wih_g, w.x, g.x), fmaf(wih_g, w.y, g.y));
            wox[c] = pk2(fmaf(wih_o, w.x, o.x), fmaf(wih_o, w.y, o.y));
        }
    }

    // per-unit constants
    float biasv[4];
    {
        int rows[4] = {p, 128 + p, 256 + p, 384 + p};
#pragma unroll
        for (int q = 0; q < 4; ++q)
            biasv[q] = b_ih[rows[q]] + b_hh[rows[q]] + W_ih[rows[q]] * blin;
    }
    const float wlin_p = W_lin[p];
    float c_state = 0.0f;
    float hn_prev = 0.0f;

    // constant pointers
    const ulonglong2* W2 = (const ulonglong2*)(sm + WS_OFF + p * W_PITCH + ks * KH);
    const ulonglong2* W3 = (const ulonglong2*)(sm + WS_OFF + (128 + p) * W_PITCH + ks * KH);
    const int hwr0 = HBUF + ks * HB_B + (p >> 6) * KH + (p & 63);

    __syncthreads();

    int step = 0;

    // ---- peeled step 0 (with one-time rank-1 correction) ---------------------
    {
        float xb;
        {
            float acc = 0.0f;
            const float* hb = sm + HBUF + ks * HB_B;
#pragma unroll 8
            for (int j = 0; j < 128; ++j)
                acc = fmaf(hb[(j >> 6) * KH + (j & 63)], W_lin[j], acc);
            xb = -(acc + blin);
        }
        const float w0 = W_ih[p], w1 = W_ih[128 + p],
                    w2c = W_ih[256 + p], w3c = W_ih[384 + p];
        STEP_BODY(0, false,
                  gI += xb * w0; gF += xb * w1; gG += xb * w2c; gO += xb * w3c;)
        ++step;
    }
    // ---- peeled step 1 -------------------------------------------------------
    STEP_BODY(1, true, ;)
    ++step;

    // ---- steps 2..2047: 2x-unrolled loop -------------------------------------
#pragma unroll 1
    for (int it = 0; it < (T_STEPS - 2) / 2; ++it) {
        STEP_BODY(0, true, ;)
        ++step;
        STEP_BODY(1, true, ;)
        ++step;
    }

    // ---- final y partials for step T-1 ---------------------------------------
    {
        float py = hn_prev * wlin_p;
        py += __shfl_xor_sync(0xffffffffu, py, 2);
        py += __shfl_xor_sync(0xffffffffu, py, 4);
        py += __shfl_xor_sync(0xffffffffu, py, 8);
        py += __shfl_xor_sync(0xffffffffu, py, 16);
        if (lane < 2)
            g_ypart[(T_STEPS - 1) * 2048 + cta * 16 + lane * 8 + (t >> 5)] = py;
    }
}

// Fold kernel: out[s, 2c+b] = sum_w g_ypart[s][c][b*8+w] + b_lin
__global__ void y_fold_kernel(float* __restrict__ out,
                              const float* __restrict__ b_lin)
{
    const int s = blockIdx.x;
    const int i = threadIdx.x;                 // 0..255 -> (cta = i>>1, b = i&1)
    const float* yp = g_ypart + s * 2048 + (i >> 1) * 16 + (i & 1) * 8;
    float v = ((yp[0] + yp[1]) + (yp[2] + yp[3]))
            + ((yp[4] + yp[5]) + (yp[6] + yp[7]));
    out[s * NB + i] = v + b_lin[0];
}

extern "C" void kernel_launch(void* const* d_in, const int* in_sizes, int n_in,
                              void* d_out, int out_size) {
    // metadata order: input, label, h0, W_ih, W_hh, b_ih, b_hh, W_lin, b_lin
    const int*   label  = (const int*)  d_in[1];
    const float* h0     = (const float*)d_in[2];
    const float* W_ih   = (const float*)d_in[3];
    const float* W_hh   = (const float*)d_in[4];
    const float* b_ih   = (const float*)d_in[5];
    const float* b_hh   = (const float*)d_in[6];
    const float* W_lin  = (const float*)d_in[7];
    const float* b_lin  = (const float*)d_in[8];
    float* out = (float*)d_out;

    cudaFuncSetAttribute(lstm_seq_kernel,
                         cudaFuncAttributeMaxDynamicSharedMemorySize, SMEM_BYTES);
    lstm_seq_kernel<<<128, THREADS, SMEM_BYTES>>>(label, h0, W_ih, W_hh,
                                                  b_ih, b_hh, W_lin, b_lin);
    y_fold_kernel<<<T_STEPS, 256>>>(out, b_lin);
}